// round 5
// baseline (speedup 1.0000x reference)
#include <cuda_runtime.h>
#include <cuda_bf16.h>
#include <math.h>

#define BATCHN 256
#define SEQN   512
#define IN_DIM 64
#define HID    256
#define NCTA   148
#define NTHR   128
#define BM     32
#define BN     64
#define BK     32

// ---------------- persistent device state (no allocation allowed) -----------
__device__ float g_x[(size_t)BATCHN * SEQN * IN_DIM];   // sanitized input
__device__ float g_h0buf[2][BATCHN * HID];
__device__ float g_h1[BATCHN * HID];
__device__ float g_z0[BATCHN * HID];
__device__ float g_rh0[BATCHN * HID];
__device__ float g_z1[BATCHN * HID];
__device__ float g_rh1[BATCHN * HID];

__device__ unsigned g_count = 0;          // always returns to 0
__device__ volatile unsigned g_gen = 0;   // monotonic generation counter

// ---------------------------- grid barrier ----------------------------------
__device__ __forceinline__ void grid_sync() {
    __syncthreads();
    if (threadIdx.x == 0) {
        __threadfence();                    // release our global writes
        unsigned gen = g_gen;               // read BEFORE arriving
        unsigned a = atomicAdd(&g_count, 1u);
        if (a == NCTA - 1) {
            g_count = 0;
            __threadfence();
            g_gen = gen + 1;                // release everyone
        } else {
            while (g_gen == gen) { __nanosleep(32); }
            __threadfence();                // acquire
        }
    }
    __syncthreads();
}

// ---------------------------- shared memory ---------------------------------
struct __align__(16) SmemT {
    float ws[2][BK][BN];   // W tiles (k-major)            16 KB
    float as[2][BM][BK];   // A tiles (m-major)             8 KB
    float red[8];
};

__device__ __forceinline__ void cp16(void* dst_smem, const void* src_gmem) {
    unsigned u = (unsigned)__cvta_generic_to_shared(dst_smem);
    asm volatile("cp.async.cg.shared.global [%0], [%1], 16;"
                 :: "r"(u), "l"(src_gmem) : "memory");
}

// Load one BKxBN W tile + one BMxBK A tile into stage `buf` for k-offset k0.
__device__ __forceinline__ void load_stage(
    SmemT* s, int buf, int k0, int tileM, int tileN,
    const float* A0, int ldA0, const float* A1, int ldA1, int K0,
    const float* W, int ldW)
{
    const int tid = threadIdx.x;
    const float* Ab; int ldA; int kb;
    if (k0 < K0) { Ab = A0; ldA = ldA0; kb = k0; }
    else         { Ab = A1; ldA = ldA1; kb = k0 - K0; }
    Ab += (size_t)tileM * BM * ldA;
    const float* Wb = W + (size_t)k0 * ldW + tileN * BN;
    // W tile: 32k x 64n = 512 float4 -> 4 per thread
#pragma unroll
    for (int q = 0; q < 4; q++) {
        int lin = q * NTHR + tid;
        int k = lin >> 4, n4 = lin & 15;
        cp16(&s->ws[buf][k][n4 * 4], Wb + (size_t)k * ldW + n4 * 4);
    }
    // A tile: 32m x 32k = 256 float4 -> 2 per thread
#pragma unroll
    for (int q = 0; q < 2; q++) {
        int lin = q * NTHR + tid;
        int m = lin >> 3, k4 = lin & 7;
        cp16(&s->as[buf][m][k4 * 4], Ab + (size_t)m * ldA + kb + k4 * 4);
    }
    asm volatile("cp.async.commit_group;" ::: "memory");
}

// One 32x64 tile of C = [A0 | A1] @ W + bias, with fused GRU epilogue.
//   is_gate: sigmoid; n<HID -> zbuf, n>=HID -> rbuf = sig * hs
//   !is_gate (candidate): hw = (1-z)*hs + z*tanh(v)
__device__ void gemm_tile(
    SmemT* s, int tileM, int tileN,
    const float* A0, int ldA0, const float* A1, int ldA1, int K0, int K,
    const float* W, int ldW, const float* bias,
    bool is_gate, float* zbuf, float* rbuf, const float* hs, float* hw)
{
    const int tid = threadIdx.x;
    const int tm = tid >> 4;     // 0..7
    const int tn = tid & 15;     // 0..15

    float acc[4][4];
#pragma unroll
    for (int i = 0; i < 4; i++)
#pragma unroll
        for (int j = 0; j < 4; j++) acc[i][j] = 0.f;

    const int nst = K / BK;
    load_stage(s, 0, 0, tileM, tileN, A0, ldA0, A1, ldA1, K0, W, ldW);

    for (int stg = 0; stg < nst; ++stg) {
        int buf = stg & 1;
        if (stg + 1 < nst) {
            load_stage(s, buf ^ 1, (stg + 1) * BK, tileM, tileN,
                       A0, ldA0, A1, ldA1, K0, W, ldW);
            asm volatile("cp.async.wait_group 1;" ::: "memory");
        } else {
            asm volatile("cp.async.wait_group 0;" ::: "memory");
        }
        __syncthreads();
#pragma unroll
        for (int w0 = 0; w0 < BK; w0 += 8) {
            float aw[4][8];
#pragma unroll
            for (int i = 0; i < 4; i++) {
                float4 p0 = *(const float4*)&s->as[buf][tm * 4 + i][w0];
                float4 p1 = *(const float4*)&s->as[buf][tm * 4 + i][w0 + 4];
                aw[i][0] = p0.x; aw[i][1] = p0.y; aw[i][2] = p0.z; aw[i][3] = p0.w;
                aw[i][4] = p1.x; aw[i][5] = p1.y; aw[i][6] = p1.z; aw[i][7] = p1.w;
            }
#pragma unroll
            for (int kk = 0; kk < 8; kk++) {
                float4 wv = *(const float4*)&s->ws[buf][w0 + kk][tn * 4];
#pragma unroll
                for (int i = 0; i < 4; i++) {
                    acc[i][0] += aw[i][kk] * wv.x;
                    acc[i][1] += aw[i][kk] * wv.y;
                    acc[i][2] += aw[i][kk] * wv.z;
                    acc[i][3] += aw[i][kk] * wv.w;
                }
            }
        }
        __syncthreads();
    }

    const int b0 = tileM * BM + tm * 4;
    const int n0 = tileN * BN + tn * 4;
#pragma unroll
    for (int i = 0; i < 4; i++) {
        int b = b0 + i;
#pragma unroll
        for (int j = 0; j < 4; j++) {
            int n = n0 + j;
            float v = acc[i][j] + bias[n];
            if (is_gate) {
                float sg = 1.f / (1.f + expf(-v));
                if (n < HID) zbuf[b * HID + n] = sg;
                else {
                    int c = n - HID;
                    rbuf[b * HID + c] = sg * hs[b * HID + c];
                }
            } else {
                float ht = tanhf(v);
                float z = zbuf[b * HID + n];
                hw[b * HID + n] = (1.f - z) * hs[b * HID + n] + z * ht;
            }
        }
    }
}

// ---------------------------- persistent kernel -----------------------------
__global__ void __launch_bounds__(NTHR, 1)
rnn_kernel(const float* __restrict__ x,
           const float* __restrict__ Wz0, const float* __restrict__ bz0,
           const float* __restrict__ Wc0, const float* __restrict__ bc0,
           const float* __restrict__ Wz1, const float* __restrict__ bz1,
           const float* __restrict__ Wc1, const float* __restrict__ bc1,
           const float* __restrict__ gamma, const float* __restrict__ beta,
           float* __restrict__ out)
{
    __shared__ SmemT s;

    // ---- init: sanitize x (NaN->0, Inf->sign*10), zero states ----
    {
        int gtid = blockIdx.x * NTHR + threadIdx.x;
        int gs = NCTA * NTHR;
        for (size_t i = gtid; i < (size_t)BATCHN * SEQN * IN_DIM; i += gs) {
            float v = x[i];
            if (v != v) v = 0.f;
            else if (isinf(v)) v = (v > 0.f) ? 10.f : -10.f;
            g_x[i] = v;
        }
        for (int i = gtid; i < BATCHN * HID; i += gs) {
            g_h0buf[0][i] = 0.f;
            g_h1[i] = 0.f;
        }
    }
    grid_sync();

    // superstep st: phase A = gates0(st) || gates1(st-1)
    //               phase B = cand0(st)  || cand1(st-1)
    for (int st = 0; st <= SEQN; ++st) {
        float* h0cur = g_h0buf[st & 1];
        float* h0nxt = g_h0buf[(st + 1) & 1];
        const float* xt = g_x + (size_t)st * IN_DIM;   // row stride SEQN*IN_DIM

        // ---------------- phase A ----------------
        {
            int nA = (st < SEQN) ? 64 : 0;   // gates0: 8x8 tiles (N=512,K=320)
            int nB = (st > 0)    ? 64 : 0;   // gates1: 8x8 tiles (N=512,K=512)
            int tot = nA + nB;
            for (int idx = blockIdx.x; idx < tot; idx += NCTA) {
                if (idx < nA) {
                    gemm_tile(&s, idx >> 3, idx & 7,
                              h0cur, HID, xt, SEQN * IN_DIM, HID, HID + IN_DIM,
                              Wz0, 3 * HID, bz0,
                              true, g_z0, g_rh0, h0cur, nullptr);
                } else {
                    int j = idx - nA;
                    gemm_tile(&s, j >> 3, j & 7,
                              g_h1, HID, h0cur, HID, HID, 2 * HID,
                              Wz1, 3 * HID, bz1,
                              true, g_z1, g_rh1, g_h1, nullptr);
                }
            }
        }
        grid_sync();

        // ---------------- phase B ----------------
        {
            int nC = (st < SEQN) ? 32 : 0;   // cand0: 8x4 tiles (N=256,K=320)
            int nD = (st > 0)    ? 32 : 0;   // cand1: 8x4 tiles (N=256,K=512)
            int tot = nC + nD;
            for (int idx = blockIdx.x; idx < tot; idx += NCTA) {
                if (idx < nC) {
                    gemm_tile(&s, idx >> 2, idx & 3,
                              g_rh0, HID, xt, SEQN * IN_DIM, HID, HID + IN_DIM,
                              Wc0, HID, bc0,
                              false, g_z0, nullptr, h0cur, h0nxt);
                } else {
                    int j = idx - nC;
                    gemm_tile(&s, j >> 2, j & 3,
                              g_rh1, HID, h0cur, HID, HID, 2 * HID,
                              Wc1, HID, bc1,
                              false, g_z1, nullptr, g_h1, g_h1);
                }
            }
        }
        grid_sync();
    }

    // ---------------- LayerNorm on final h1 ----------------
    {
        const int tid = threadIdx.x;
        const int wid = tid >> 5, lane = tid & 31;
        for (int b = blockIdx.x; b < BATCHN; b += NCTA) {
            float v0 = g_h1[b * HID + tid];
            float v1 = g_h1[b * HID + tid + NTHR];
            float sum = v0 + v1;
            float sq  = v0 * v0 + v1 * v1;
#pragma unroll
            for (int off = 16; off; off >>= 1) {
                sum += __shfl_xor_sync(0xFFFFFFFFu, sum, off);
                sq  += __shfl_xor_sync(0xFFFFFFFFu, sq,  off);
            }
            if (lane == 0) { s.red[wid] = sum; s.red[4 + wid] = sq; }
            __syncthreads();
            float ts = s.red[0] + s.red[1] + s.red[2] + s.red[3];
            float tq = s.red[4] + s.red[5] + s.red[6] + s.red[7];
            float mean = ts * (1.f / HID);
            float var  = tq * (1.f / HID) - mean * mean;
            float rstd = rsqrtf(var + 1e-5f);
            out[b * HID + tid]        = (v0 - mean) * rstd * gamma[tid] + beta[tid];
            out[b * HID + tid + NTHR] = (v1 - mean) * rstd * gamma[tid + NTHR] + beta[tid + NTHR];
            __syncthreads();
        }
    }
}

extern "C" void kernel_launch(void* const* d_in, const int* in_sizes, int n_in,
                              void* d_out, int out_size) {
    (void)in_sizes; (void)n_in; (void)out_size;
    const float* x     = (const float*)d_in[0];
    const float* Wz0   = (const float*)d_in[1];
    const float* bz0   = (const float*)d_in[2];
    const float* Wc0   = (const float*)d_in[3];
    const float* bc0   = (const float*)d_in[4];
    const float* Wz1   = (const float*)d_in[5];
    const float* bz1   = (const float*)d_in[6];
    const float* Wc1   = (const float*)d_in[7];
    const float* bc1   = (const float*)d_in[8];
    const float* gamma = (const float*)d_in[9];
    const float* beta  = (const float*)d_in[10];
    float* out = (float*)d_out;

    rnn_kernel<<<NCTA, NTHR>>>(x, Wz0, bz0, Wc0, bc0,
                               Wz1, bz1, Wc1, bc1, gamma, beta, out);
}